// round 14
// baseline (speedup 1.0000x reference)
#include <cuda_runtime.h>
#include <cstdint>

#define B_   128
#define T_   64
#define V_   1024
#define TS_  64
#define H_   512
#define NTOK (B_ * T_)      // 8192
#define G3   (3 * H_)       // 1536
#define IN_  (V_ + TS_)     // 1088

typedef unsigned long long ull;

// ---------------- packed fp32x2 helpers (Blackwell) ----------------
__device__ __forceinline__ ull ffma2(ull a, ull b, ull c) {
    ull d;
    asm("fma.rn.f32x2 %0, %1, %2, %3;" : "=l"(d) : "l"(a), "l"(b), "l"(c));
    return d;
}
__device__ __forceinline__ ull dup2(float a) {
    ull d; unsigned u = __float_as_uint(a);
    asm("mov.b64 %0, {%1, %2};" : "=l"(d) : "r"(u), "r"(u));
    return d;
}
__device__ __forceinline__ float2 u2f(ull a) {
    float2 f; unsigned lo, hi;
    asm("mov.b64 {%0, %1}, %2;" : "=r"(lo), "=r"(hi) : "l"(a));
    f.x = __uint_as_float(lo); f.y = __uint_as_float(hi);
    return f;
}
__device__ __forceinline__ float tanhfast(float x) {
    float y; asm("tanh.approx.f32 %0, %1;" : "=f"(y) : "f"(x)); return y;
}

// ---------------- device scratch ----------------
__device__ float    g_xg[NTOK * G3];
__device__ unsigned g_ready[64];          // per 128-token row-tile: #col-tiles done

// ---------------- layout constants ----------------
#define SCAN_CTAS   16
#define GEMM_BLOCKS 768                   // 64 row-tiles x 12 col-tiles
#define GRID_X      (SCAN_CTAS + GEMM_BLOCKS)

#define BM 128
#define BN 128
#define BK 16
#define AST 132

// scan smem layout (dynamic): mbars | wsm(n1 row) | hb | stage | bhh | lens
#define SMEM_MBARS  0
#define SMEM_WSM    32
#define WSM_BYTES   32768                 // 16w x 4qq x 32l x 2 ull
#define SMEM_HB     (SMEM_WSM + WSM_BYTES)        // 32800
#define SMEM_STAGE  (SMEM_HB + 4096)              // 36896 (16B aligned)
#define SMEM_BHH    (SMEM_STAGE + 128)
#define SMEM_LENS   (SMEM_BHH + 384)
#define SCAN_BYTES  (SMEM_LENS + 512)
// gemm smem: As | Bs | caS | ccS
#define GEMM_BYTES  (2 * BK * AST * 4 + 2 * BN * 4)
#define DYN_SMEM    ((GEMM_BYTES > SCAN_BYTES ? GEMM_BYTES : SCAN_BYTES) + 128)

// per-phase expected bytes at each dest barrier: 16 src CTAs x 128B = 2048
#define TX_BYTES 2048u

// float index of unit u (0..31) within the 32-float block of source CTA `cta`.
// The (q+cta)&3 swizzle makes every 8-lane quarter's LDS.128 addresses tile
// distinct 16B chunks mod 128B -> conflict-free matvec loads.
__device__ __forceinline__ int blkoff(int u, int cta) {
    int q = (u >> 2) & 3, r = u >> 4, e = u & 3;
    return ((q + cta) & 3) * 8 + r * 4 + e;
}

__device__ __forceinline__ void waitParityCluster(uint32_t addr, int ph) {
    asm volatile(
        "{\n\t"
        ".reg .pred p;\n\t"
        "WLOOP_%=:\n\t"
        "mbarrier.try_wait.parity.acquire.cluster.shared::cta.b64 p, [%0], %1, 0x989680;\n\t"
        "@p bra WDONE_%=;\n\t"
        "bra WLOOP_%=;\n\t"
        "WDONE_%=:\n\t"
        "}"
        :: "r"(addr), "r"(ph) : "memory");
}

// ================= GEMM body (blocks 16..783, 512 threads) =================
__device__ void gemm_body(const float* __restrict__ A,
                          const float* __restrict__ Bw,
                          const float* __restrict__ interval,
                          const float* __restrict__ W_time,
                          const float* __restrict__ b_time,
                          const float* __restrict__ b_ih,
                          char* smc)
{
    float (*As)[AST] = (float (*)[AST])smc;
    float (*Bs)[AST] = (float (*)[AST])(smc + BK * AST * 4);
    float* caS = (float*)(smc + 2 * BK * AST * 4);
    float* ccS = caS + BN;

    int tid = threadIdx.x;
    int gemmIdx = blockIdx.x - SCAN_CTAS;
    int rowTile = gemmIdx / 12;
    int colTile = gemmIdx - rowTile * 12;
    int rowBase = rowTile * BM;
    int colBase = colTile * BN;

    if (tid < BN) {
        int g = colBase + tid;
        const float* wrow = Bw + (size_t)g * IN_ + V_;
        float a = 0.f, cc = 0.f;
#pragma unroll 8
        for (int j = 0; j < TS_; j++) {
            float wv = wrow[j];
            a  += W_time[j] * wv;
            cc += b_time[j] * wv;
        }
        caS[tid] = a;
        ccS[tid] = cc + b_ih[g];
    }

    int tx = tid & 15;
    int ty = tid >> 4;
    int lr = tid >> 2;
    int kq = tid & 3;

    ull acc2[4][4];
#pragma unroll
    for (int i = 0; i < 4; i++)
#pragma unroll
        for (int j = 0; j < 4; j++) acc2[i][j] = 0ull;

    const float* Aptr = A  + (size_t)(rowBase + lr) * V_  + kq * 4;
    const float* Bptr = Bw + (size_t)(colBase + lr) * IN_ + kq * 4;

    for (int kt = 0; kt < V_; kt += BK) {
        float4 a0 = *(const float4*)(Aptr + kt);
        float4 b0 = *(const float4*)(Bptr + kt);

        __syncthreads();
        As[kq*4+0][lr] = a0.x; As[kq*4+1][lr] = a0.y; As[kq*4+2][lr] = a0.z; As[kq*4+3][lr] = a0.w;
        Bs[kq*4+0][lr] = b0.x; Bs[kq*4+1][lr] = b0.y; Bs[kq*4+2][lr] = b0.z; Bs[kq*4+3][lr] = b0.w;
        __syncthreads();

#pragma unroll
        for (int kk = 0; kk < BK; kk++) {
            float av[4];
            *(float4*)av = *(const float4*)&As[kk][ty*4];
            const ull* bp = (const ull*)&Bs[kk][tx*8];
            ull bv0 = bp[0], bv1 = bp[1], bv2 = bp[2], bv3 = bp[3];
#pragma unroll
            for (int i = 0; i < 4; i++) {
                ull a2 = dup2(av[i]);
                acc2[i][0] = ffma2(a2, bv0, acc2[i][0]);
                acc2[i][1] = ffma2(a2, bv1, acc2[i][1]);
                acc2[i][2] = ffma2(a2, bv2, acc2[i][2]);
                acc2[i][3] = ffma2(a2, bv3, acc2[i][3]);
            }
        }
    }

    float ai[4], ca[8], cc[8];
#pragma unroll
    for (int i = 0; i < 4; i++) ai[i] = interval[rowBase + ty*4 + i];
#pragma unroll
    for (int j = 0; j < 8; j++) {
        ca[j] = caS[tx*8 + j];
        cc[j] = ccS[tx*8 + j];
    }
#pragma unroll
    for (int i = 0; i < 4; i++) {
        size_t rbase = (size_t)(rowBase + ty*4 + i) * G3 + colBase + tx*8;
#pragma unroll
        for (int q = 0; q < 2; q++) {
            float2 v0 = u2f(acc2[i][2*q+0]);
            float2 v1 = u2f(acc2[i][2*q+1]);
            float4 o;
            o.x = v0.x + ai[i] * ca[4*q+0] + cc[4*q+0];
            o.y = v0.y + ai[i] * ca[4*q+1] + cc[4*q+1];
            o.z = v1.x + ai[i] * ca[4*q+2] + cc[4*q+2];
            o.w = v1.y + ai[i] * ca[4*q+3] + cc[4*q+3];
            *(float4*)&g_xg[rbase + 4*q] = o;
        }
    }

    __syncthreads();
    if (tid == 0) {
        __threadfence();
        atomicAdd(&g_ready[rowTile], 1u);
    }
}

// ================= scan body (blocks 0..15, one 16-CTA cluster) =================
// R13 skeleton (bulk publish, block layout) with:
//  - 5 W_hh rows in registers + n1 row in conflict-free smem -> no spills
//  - xg prefetched at loop bottom (~1 step early; within-sample tile is
//    always ready, so prefetch is ready-safe; sample-first token loads at top)
__device__ void scan_body(const float* __restrict__ W_hh,
                          const float* __restrict__ b_hh,
                          const int*   __restrict__ lens,
                          float*       __restrict__ out,
                          char* smc)
{
    ull*   wsm     = (ull*)(smc + SMEM_WSM);        // n1 weight row
    float* hb      = (float*)(smc + SMEM_HB);       // [2][512] block layout
    float* stage   = (float*)(smc + SMEM_STAGE);    // 32 floats, 16B aligned
    float* bhh     = (float*)(smc + SMEM_BHH);
    int*   lens_sm = (int*)(smc + SMEM_LENS);
    uint32_t mb_s  = (uint32_t)__cvta_generic_to_shared(smc + SMEM_MBARS);

    int tid = threadIdx.x;
    int w = tid >> 5;
    int l = tid & 31;
    uint32_t c;
    asm("mov.u32 %0, %%cluster_ctarank;" : "=r"(c));

    hb[tid] = 0.f;
    hb[512 + tid] = 0.f;
    if (tid < 128) lens_sm[tid] = lens[tid];
    if (tid < 96) {
        int g = tid >> 5, u = tid & 31;
        bhh[tid] = b_hh[g * H_ + 32 * (int)c + u];
    }
    if (tid == 0) {
        asm volatile("mbarrier.init.shared.b64 [%0], 1;" :: "r"(mb_s)      : "memory");
        asm volatile("mbarrier.init.shared.b64 [%0], 1;" :: "r"(mb_s + 8) : "memory");
        asm volatile("mbarrier.arrive.expect_tx.shared.b64 _, [%0], %1;"
                     :: "r"(mb_s),     "r"(TX_BYTES) : "memory");
        asm volatile("mbarrier.arrive.expect_tx.shared.b64 _, [%0], %1;"
                     :: "r"(mb_s + 8), "r"(TX_BYTES) : "memory");
        asm volatile("fence.mbarrier_init.release.cluster;" ::: "memory");
    }

    int j0 = 32 * (int)c + 2 * w;

    // rows r0,r1,z0,z1,n0 in registers as f32x2 (80 regs)
    ull W2[5][8];
#pragma unroll
    for (int r = 0; r < 5; r++) {
        int row = (r < 2) ? (j0 + r) : (r < 4) ? (H_ + j0 + r - 2) : (2 * H_ + j0);
        const ull* wp = (const ull*)(W_hh + (size_t)row * H_ + 16 * l);
#pragma unroll
        for (int k = 0; k < 8; k++) W2[r][k] = wp[k];
    }
    // row n1 (2H + j0 + 1) into smem, lane-distinct 16B chunks per (w,qq)
    {
        const ull* wp = (const ull*)(W_hh + (size_t)(2 * H_ + j0 + 1) * H_ + 16 * l);
#pragma unroll
        for (int k = 0; k < 8; k++)
            wsm[(size_t)((w * 4 + (k >> 1)) * 32 + l) * 2 + (k & 1)] = wp[k];
    }
    __syncthreads();
    asm volatile("barrier.cluster.arrive.aligned;" ::: "memory");
    asm volatile("barrier.cluster.wait.aligned;"   ::: "memory");

    uint32_t hb_u    = (uint32_t)__cvta_generic_to_shared(hb);
    uint32_t stage_u = (uint32_t)__cvta_generic_to_shared(stage);
    // bulk publish addresses: warp w ships stage -> CTA w's block for source c
    uint32_t ra_blk, rb_bar0, rb_bar1;
    {
        uint32_t la = hb_u + 128u * c;      // buffer 0, block c
        asm("mapa.shared::cluster.u32 %0, %1, %2;" : "=r"(ra_blk)  : "r"(la), "r"(w));
        asm("mapa.shared::cluster.u32 %0, %1, %2;" : "=r"(rb_bar0) : "r"(mb_s),     "r"(w));
        asm("mapa.shared::cluster.u32 %0, %1, %2;" : "=r"(rb_bar1) : "r"(mb_s + 8), "r"(w));
    }

    // matvec lane addressing (block layout)
    int c_blk = l >> 1;
    int mv_base = 32 * c_blk + (l & 1) * 4;
    const ull* wn_base = wsm + (size_t)(w * 4 * 32 + l) * 2;   // +qq*64 per qq

    int p = 0, ph0 = 0, ph1 = 0;
    bool pending = false;
    int cur_tile = -1;
    float hold = 0.f;                     // previous hnew of unit j0+l (lanes 0,1)
    int stg_idx = blkoff(2 * w + (l & 1), (int)c);   // gate lane's stage slot
    float nxr = 0.f, nxz = 0.f, nxn = 0.f;
    bool pfv = false;

    for (int b = 0; b < B_; b++) {
        int len = lens_sm[b];
        pfv = false;
        for (int t = 0; t < len; t++) {
            int n = (b << 6) + t;

            // wait until this token's GEMM row-tile is complete (12 col-tiles)
            if ((n >> 7) != cur_tile) {
                cur_tile = n >> 7;
                unsigned rdy;
                do {
                    asm volatile("ld.acquire.gpu.global.u32 %0, [%1];"
                                 : "=r"(rdy) : "l"(g_ready + cur_tile) : "memory");
                } while (rdy < 12u);
            }

            // xg: prefetched at previous loop bottom, else load now (sample start)
            float xr, xz, xn;
            if (pfv) {
                xr = nxr; xz = nxz; xn = nxn;
            } else {
                xr = xz = xn = 0.f;
                if (l < 2) {
                    const float* xp = g_xg + (size_t)n * G3 + (j0 + l);
                    xr = __ldg(xp);
                    xz = __ldg(xp + H_);
                    xn = __ldg(xp + 2 * H_);
                }
            }

            // every warp waits the local barrier; thread 0 re-arms for next use
            if (pending) {
                uint32_t a = mb_s + 8u * (uint32_t)p;
                waitParityCluster(a, p ? ph1 : ph0);
                if (tid == 0)
                    asm volatile("mbarrier.arrive.expect_tx.shared.b64 _, [%0], %1;"
                                 :: "r"(a), "r"(TX_BYTES) : "memory");
                if (p) ph1 ^= 1; else ph0 ^= 1;
                pending = false;
            }

            const float* hp = hb + p * 512;

            ull acc2[6] = {0ull, 0ull, 0ull, 0ull, 0ull, 0ull};
#pragma unroll
            for (int qq = 0; qq < 4; qq++) {
                int idx = mv_base + (((qq + c_blk) & 3) << 3);
                const ull* hq = (const ull*)(hp + idx);
                ull h01 = hq[0], h23 = hq[1];
#pragma unroll
                for (int r = 0; r < 5; r++) acc2[r] = ffma2(W2[r][2*qq+0], h01, acc2[r]);
#pragma unroll
                for (int r = 0; r < 5; r++) acc2[r] = ffma2(W2[r][2*qq+1], h23, acc2[r]);
                const ull* w5 = wn_base + qq * 64;
                acc2[5] = ffma2(w5[0], h01, acc2[5]);
                acc2[5] = ffma2(w5[1], h23, acc2[5]);
            }
            float acc[6];
#pragma unroll
            for (int r = 0; r < 6; r++) { float2 f = u2f(acc2[r]); acc[r] = f.x + f.y; }

            // split-butterfly reduce: 6 + 12 + 3 SHFLs
#pragma unroll
            for (int r = 0; r < 6; r++)
                acc[r] += __shfl_xor_sync(0xffffffffu, acc[r], 16);
            bool hihalf = (l >= 16);
            float s0 = hihalf ? acc[3] : acc[0];
            float s1 = hihalf ? acc[4] : acc[1];
            float s2 = hihalf ? acc[5] : acc[2];
#pragma unroll
            for (int off = 8; off > 0; off >>= 1) {
                s0 += __shfl_xor_sync(0xffffffffu, s0, off);
                s1 += __shfl_xor_sync(0xffffffffu, s1, off);
                s2 += __shfl_xor_sync(0xffffffffu, s2, off);
            }
            float t0 = __shfl_sync(0xffffffffu, s0, 16);   // acc3
            float t1 = __shfl_sync(0xffffffffu, s1, 16);   // acc4
            float t2 = __shfl_sync(0xffffffffu, s2, 16);   // acc5

            if (l < 2) {
                int bidx = 2 * w + l;
                float a_r = l ? s1 : s0;
                float a_z = l ? t0 : s2;
                float a_n = l ? t2 : t1;
                float rr = 0.5f * tanhfast(0.5f * (xr + a_r + bhh[bidx]))      + 0.5f;
                float zz = 0.5f * tanhfast(0.5f * (xz + a_z + bhh[32 + bidx])) + 0.5f;
                float nn = tanhfast(xn + rr * (a_n + bhh[64 + bidx]));
                float hnew = fmaf(zz, hold - nn, nn);
                hold = hnew;
                stage[stg_idx] = hnew;
            }
            __syncthreads();   // stage complete; all warps done reading hb[p]

            // bulk publish: ONE 128B DSMEM copy per warp (16 tx updates/dest/step)
            if (l == 0) {
                uint32_t ra = ra_blk + (p ? 0u : 2048u);   // dest buffer p^1
                uint32_t rb = p ? rb_bar0 : rb_bar1;       // bar[p^1]
                asm volatile(
                    "cp.async.bulk.shared::cluster.shared::cta.mbarrier::complete_tx::bytes "
                    "[%0], [%1], 128, [%2];"
                    :: "r"(ra), "r"(stage_u), "r"(rb) : "memory");
            }
            p ^= 1;
            pending = true;

            // prefetch next token's xg (same sample -> same row-tile, ready-safe)
            if (t + 1 < len) {
                if (l < 2) {
                    const float* xp = g_xg + (size_t)(n + 1) * G3 + (j0 + l);
                    nxr = __ldg(xp);
                    nxz = __ldg(xp + H_);
                    nxn = __ldg(xp + 2 * H_);
                }
                pfv = true;
            } else {
                pfv = false;
            }
        }

        if (pending) {
            uint32_t a = mb_s + 8u * (uint32_t)p;
            waitParityCluster(a, p ? ph1 : ph0);
            if (tid == 0)
                asm volatile("mbarrier.arrive.expect_tx.shared.b64 _, [%0], %1;"
                             :: "r"(a), "r"(TX_BYTES) : "memory");
            if (p) ph1 ^= 1; else ph0 ^= 1;
            pending = false;
        }
        if (tid < 32) {
            out[b * H_ + 32 * (int)c + tid] =
                hb[p * 512 + 32 * (int)c + blkoff(tid, (int)c)];
        }
    }

    asm volatile("barrier.cluster.arrive.aligned;" ::: "memory");
    asm volatile("barrier.cluster.wait.aligned;"   ::: "memory");
}

// ================= fused kernel =================
__global__ void __launch_bounds__(512, 1)
fused_kernel(const float* __restrict__ visit_emb,
             const float* __restrict__ intervals,
             const float* __restrict__ W_time,
             const float* __restrict__ b_time,
             const float* __restrict__ W_ih,
             const float* __restrict__ W_hh,
             const float* __restrict__ b_ih,
             const float* __restrict__ b_hh,
             const int*   __restrict__ lens,
             float*       __restrict__ out)
{
    extern __shared__ char smc[];
    if (blockIdx.x >= SCAN_CTAS) {
        gemm_body(visit_emb, W_ih, intervals, W_time, b_time, b_ih, smc);
    } else {
        scan_body(W_hh, b_hh, lens, out, smc);
    }
}

// ---------------- launcher ----------------
extern "C" void kernel_launch(void* const* d_in, const int* in_sizes, int n_in,
                              void* d_out, int out_size)
{
    const float* visit_emb = (const float*)d_in[0];
    const float* intervals = (const float*)d_in[1];
    const float* W_time    = (const float*)d_in[2];
    const float* b_time    = (const float*)d_in[3];
    const float* W_ih      = (const float*)d_in[4];
    const float* W_hh      = (const float*)d_in[5];
    const float* b_ih      = (const float*)d_in[6];
    const float* b_hh      = (const float*)d_in[7];
    const int*   lens      = (const int*)d_in[8];
    float* out = (float*)d_out;

    void* readyPtr = nullptr;
    cudaGetSymbolAddress(&readyPtr, g_ready);
    cudaMemsetAsync(readyPtr, 0, 64 * sizeof(unsigned));

    cudaFuncSetAttribute(fused_kernel, cudaFuncAttributeNonPortableClusterSizeAllowed, 1);
    cudaFuncSetAttribute(fused_kernel, cudaFuncAttributeMaxDynamicSharedMemorySize, DYN_SMEM);

    cudaLaunchConfig_t cfg = {};
    cfg.gridDim  = dim3(GRID_X, 1, 1);
    cfg.blockDim = dim3(512, 1, 1);
    cfg.dynamicSmemBytes = DYN_SMEM;
    cfg.stream = 0;
    cudaLaunchAttribute attrs[1];
    attrs[0].id = cudaLaunchAttributeClusterDimension;
    attrs[0].val.clusterDim.x = 16;
    attrs[0].val.clusterDim.y = 1;
    attrs[0].val.clusterDim.z = 1;
    cfg.attrs = attrs;
    cfg.numAttrs = 1;

    cudaLaunchKernelEx(&cfg, fused_kernel,
                       visit_emb, intervals, W_time, b_time, W_ih, W_hh,
                       b_ih, b_hh, lens, out);
}

// round 15
// speedup vs baseline: 1.0775x; 1.0775x over previous
#include <cuda_runtime.h>
#include <cstdint>

#define B_   128
#define T_   64
#define V_   1024
#define TS_  64
#define H_   512
#define NTOK (B_ * T_)      // 8192
#define G3   (3 * H_)       // 1536
#define IN_  (V_ + TS_)     // 1088

typedef unsigned long long ull;

// ---------------- packed fp32x2 helpers (Blackwell) ----------------
__device__ __forceinline__ ull ffma2(ull a, ull b, ull c) {
    ull d;
    asm("fma.rn.f32x2 %0, %1, %2, %3;" : "=l"(d) : "l"(a), "l"(b), "l"(c));
    return d;
}
__device__ __forceinline__ ull dup2(float a) {
    ull d; unsigned u = __float_as_uint(a);
    asm("mov.b64 %0, {%1, %2};" : "=l"(d) : "r"(u), "r"(u));
    return d;
}
__device__ __forceinline__ float2 u2f(ull a) {
    float2 f; unsigned lo, hi;
    asm("mov.b64 {%0, %1}, %2;" : "=r"(lo), "=r"(hi) : "l"(a));
    f.x = __uint_as_float(lo); f.y = __uint_as_float(hi);
    return f;
}
__device__ __forceinline__ float tanhfast(float x) {
    float y; asm("tanh.approx.f32 %0, %1;" : "=f"(y) : "f"(x)); return y;
}

// ---------------- device scratch ----------------
__device__ float    g_xg[NTOK * G3];
__device__ unsigned g_ready[64];          // per 128-token row-tile: #col-tiles done

// ---------------- layout constants ----------------
#define SCAN_CTAS   16
#define GEMM_BLOCKS 768                   // 64 row-tiles x 12 col-tiles
#define GRID_X      (SCAN_CTAS + GEMM_BLOCKS)

#define BM 128
#define BN 128
#define BK 16
#define AST 132

// scan smem layout (dynamic): mbars | hb | stage | bhh | lens
#define SMEM_MBARS  0
#define SMEM_HB     32
#define SMEM_STAGE  (SMEM_HB + 4096)      // 4128: 16B-aligned (cp.async.bulk src)
#define SMEM_BHH    (SMEM_STAGE + 128)
#define SMEM_LENS   (SMEM_BHH + 384)
#define SCAN_BYTES  (SMEM_LENS + 512)
// gemm smem: As | Bs | caS | ccS
#define GEMM_BYTES  (2 * BK * AST * 4 + 2 * BN * 4)
#define DYN_SMEM    ((GEMM_BYTES > SCAN_BYTES ? GEMM_BYTES : SCAN_BYTES) + 128)

// per-phase expected bytes at each dest barrier: 16 src CTAs x 128B = 2048
#define TX_BYTES 2048u

// float index of unit u (0..31) within the 32-float block of source CTA `cta`.
// The (q+cta)&3 swizzle makes every 8-lane quarter's LDS.128 addresses tile
// distinct 16B chunks mod 128B -> conflict-free matvec loads.
__device__ __forceinline__ int blkoff(int u, int cta) {
    int q = (u >> 2) & 3, r = u >> 4, e = u & 3;
    return ((q + cta) & 3) * 8 + r * 4 + e;
}

__device__ __forceinline__ void waitParityCluster(uint32_t addr, int ph) {
    asm volatile(
        "{\n\t"
        ".reg .pred p;\n\t"
        "WLOOP_%=:\n\t"
        "mbarrier.try_wait.parity.acquire.cluster.shared::cta.b64 p, [%0], %1, 0x989680;\n\t"
        "@p bra WDONE_%=;\n\t"
        "bra WLOOP_%=;\n\t"
        "WDONE_%=:\n\t"
        "}"
        :: "r"(addr), "r"(ph) : "memory");
}

// ================= GEMM body (blocks 16..783, 512 threads) =================
__device__ void gemm_body(const float* __restrict__ A,
                          const float* __restrict__ Bw,
                          const float* __restrict__ interval,
                          const float* __restrict__ W_time,
                          const float* __restrict__ b_time,
                          const float* __restrict__ b_ih,
                          char* smc)
{
    float (*As)[AST] = (float (*)[AST])smc;
    float (*Bs)[AST] = (float (*)[AST])(smc + BK * AST * 4);
    float* caS = (float*)(smc + 2 * BK * AST * 4);
    float* ccS = caS + BN;

    int tid = threadIdx.x;
    int gemmIdx = blockIdx.x - SCAN_CTAS;
    int rowTile = gemmIdx / 12;
    int colTile = gemmIdx - rowTile * 12;
    int rowBase = rowTile * BM;
    int colBase = colTile * BN;

    if (tid < BN) {
        int g = colBase + tid;
        const float* wrow = Bw + (size_t)g * IN_ + V_;
        float a = 0.f, cc = 0.f;
#pragma unroll 8
        for (int j = 0; j < TS_; j++) {
            float wv = wrow[j];
            a  += W_time[j] * wv;
            cc += b_time[j] * wv;
        }
        caS[tid] = a;
        ccS[tid] = cc + b_ih[g];
    }

    int tx = tid & 15;
    int ty = tid >> 4;
    int lr = tid >> 2;
    int kq = tid & 3;

    ull acc2[4][4];
#pragma unroll
    for (int i = 0; i < 4; i++)
#pragma unroll
        for (int j = 0; j < 4; j++) acc2[i][j] = 0ull;

    const float* Aptr = A  + (size_t)(rowBase + lr) * V_  + kq * 4;
    const float* Bptr = Bw + (size_t)(colBase + lr) * IN_ + kq * 4;

    for (int kt = 0; kt < V_; kt += BK) {
        float4 a0 = *(const float4*)(Aptr + kt);
        float4 b0 = *(const float4*)(Bptr + kt);

        __syncthreads();
        As[kq*4+0][lr] = a0.x; As[kq*4+1][lr] = a0.y; As[kq*4+2][lr] = a0.z; As[kq*4+3][lr] = a0.w;
        Bs[kq*4+0][lr] = b0.x; Bs[kq*4+1][lr] = b0.y; Bs[kq*4+2][lr] = b0.z; Bs[kq*4+3][lr] = b0.w;
        __syncthreads();

#pragma unroll
        for (int kk = 0; kk < BK; kk++) {
            float av[4];
            *(float4*)av = *(const float4*)&As[kk][ty*4];
            const ull* bp = (const ull*)&Bs[kk][tx*8];
            ull bv0 = bp[0], bv1 = bp[1], bv2 = bp[2], bv3 = bp[3];
#pragma unroll
            for (int i = 0; i < 4; i++) {
                ull a2 = dup2(av[i]);
                acc2[i][0] = ffma2(a2, bv0, acc2[i][0]);
                acc2[i][1] = ffma2(a2, bv1, acc2[i][1]);
                acc2[i][2] = ffma2(a2, bv2, acc2[i][2]);
                acc2[i][3] = ffma2(a2, bv3, acc2[i][3]);
            }
        }
    }

    float ai[4], ca[8], cc[8];
#pragma unroll
    for (int i = 0; i < 4; i++) ai[i] = interval[rowBase + ty*4 + i];
#pragma unroll
    for (int j = 0; j < 8; j++) {
        ca[j] = caS[tx*8 + j];
        cc[j] = ccS[tx*8 + j];
    }
#pragma unroll
    for (int i = 0; i < 4; i++) {
        size_t rbase = (size_t)(rowBase + ty*4 + i) * G3 + colBase + tx*8;
#pragma unroll
        for (int q = 0; q < 2; q++) {
            float2 v0 = u2f(acc2[i][2*q+0]);
            float2 v1 = u2f(acc2[i][2*q+1]);
            float4 o;
            o.x = v0.x + ai[i] * ca[4*q+0] + cc[4*q+0];
            o.y = v0.y + ai[i] * ca[4*q+1] + cc[4*q+1];
            o.z = v1.x + ai[i] * ca[4*q+2] + cc[4*q+2];
            o.w = v1.y + ai[i] * ca[4*q+3] + cc[4*q+3];
            *(float4*)&g_xg[rbase + 4*q] = o;
        }
    }

    __syncthreads();
    if (tid == 0) {
        __threadfence();
        atomicAdd(&g_ready[rowTile], 1u);
    }
}

// ================= scan body (blocks 0..15, one 16-CTA cluster) =================
// R13 design (bulk publish, block layout, 6 reg-resident weight rows) with
// straggler fixes: mbarrier re-arm moved post-publish (off warp0's pre-matvec
// path; safe — bar[p]'s refill comes from step-s+1 publishers, each gated on
// our step-s publish plus a full body), and out-writes moved to warp 1.
__device__ void scan_body(const float* __restrict__ W_hh,
                          const float* __restrict__ b_hh,
                          const int*   __restrict__ lens,
                          float*       __restrict__ out,
                          char* smc)
{
    float* hb      = (float*)(smc + SMEM_HB);       // [2][512] block layout
    float* stage   = (float*)(smc + SMEM_STAGE);    // 32 floats, 16B aligned
    float* bhh     = (float*)(smc + SMEM_BHH);
    int*   lens_sm = (int*)(smc + SMEM_LENS);
    uint32_t mb_s  = (uint32_t)__cvta_generic_to_shared(smc + SMEM_MBARS);

    int tid = threadIdx.x;
    int w = tid >> 5;
    int l = tid & 31;
    uint32_t c;
    asm("mov.u32 %0, %%cluster_ctarank;" : "=r"(c));

    hb[tid] = 0.f;
    hb[512 + tid] = 0.f;
    if (tid < 128) lens_sm[tid] = lens[tid];
    if (tid < 96) {
        int g = tid >> 5, u = tid & 31;
        bhh[tid] = b_hh[g * H_ + 32 * (int)c + u];
    }
    if (tid == 0) {
        asm volatile("mbarrier.init.shared.b64 [%0], 1;" :: "r"(mb_s)      : "memory");
        asm volatile("mbarrier.init.shared.b64 [%0], 1;" :: "r"(mb_s + 8) : "memory");
        asm volatile("mbarrier.arrive.expect_tx.shared.b64 _, [%0], %1;"
                     :: "r"(mb_s),     "r"(TX_BYTES) : "memory");
        asm volatile("mbarrier.arrive.expect_tx.shared.b64 _, [%0], %1;"
                     :: "r"(mb_s + 8), "r"(TX_BYTES) : "memory");
        asm volatile("fence.mbarrier_init.release.cluster;" ::: "memory");
    }

    int j0 = 32 * (int)c + 2 * w;

    // all 6 W_hh rows (r0,r1,z0,z1,n0,n1) register-resident as f32x2
    ull W2[6][8];
#pragma unroll
    for (int r = 0; r < 6; r++) {
        int row = (r < 2) ? (j0 + r) : (r < 4) ? (H_ + j0 + r - 2) : (2 * H_ + j0 + r - 4);
        const ull* wp = (const ull*)(W_hh + (size_t)row * H_ + 16 * l);
#pragma unroll
        for (int k = 0; k < 8; k++) W2[r][k] = wp[k];
    }
    __syncthreads();
    asm volatile("barrier.cluster.arrive.aligned;" ::: "memory");
    asm volatile("barrier.cluster.wait.aligned;"   ::: "memory");

    uint32_t hb_u    = (uint32_t)__cvta_generic_to_shared(hb);
    uint32_t stage_u = (uint32_t)__cvta_generic_to_shared(stage);
    // bulk publish addresses: warp w ships stage -> CTA w's block for source c
    uint32_t ra_blk, rb_bar0, rb_bar1;
    {
        uint32_t la = hb_u + 128u * c;      // buffer 0, block c
        asm("mapa.shared::cluster.u32 %0, %1, %2;" : "=r"(ra_blk)  : "r"(la), "r"(w));
        asm("mapa.shared::cluster.u32 %0, %1, %2;" : "=r"(rb_bar0) : "r"(mb_s),     "r"(w));
        asm("mapa.shared::cluster.u32 %0, %1, %2;" : "=r"(rb_bar1) : "r"(mb_s + 8), "r"(w));
    }

    // matvec lane addressing (block layout)
    int c_blk = l >> 1;
    int mv_base = 32 * c_blk + (l & 1) * 4;

    int p = 0, ph0 = 0, ph1 = 0;
    bool pending = false;
    int cur_tile = -1;
    float hold = 0.f;                     // previous hnew of unit j0+l (lanes 0,1)
    int stg_idx = blkoff(2 * w + (l & 1), (int)c);   // gate lane's stage slot

    for (int b = 0; b < B_; b++) {
        int len = lens_sm[b];
        for (int t = 0; t < len; t++) {
            int n = (b << 6) + t;

            // wait until this token's GEMM row-tile is complete (12 col-tiles)
            if ((n >> 7) != cur_tile) {
                cur_tile = n >> 7;
                unsigned rdy;
                do {
                    asm volatile("ld.acquire.gpu.global.u32 %0, [%1];"
                                 : "=r"(rdy) : "l"(g_ready + cur_tile) : "memory");
                } while (rdy < 12u);
            }

            // xg loads issued before the sync wait (latency hidden under it)
            float xr = 0.f, xz = 0.f, xn = 0.f;
            if (l < 2) {
                const float* xp = g_xg + (size_t)n * G3 + (j0 + l);
                xr = __ldg(xp);
                xz = __ldg(xp + H_);
                xn = __ldg(xp + 2 * H_);
            }

            // consumer wait (re-arm deferred to post-publish, off the
            // pre-matvec critical path of warp 0)
            bool did_wait = pending;
            if (pending) {
                uint32_t a = mb_s + 8u * (uint32_t)p;
                waitParityCluster(a, p ? ph1 : ph0);
                if (p) ph1 ^= 1; else ph0 ^= 1;
                pending = false;
            }

            const float* hp = hb + p * 512;

            ull acc2[6] = {0ull, 0ull, 0ull, 0ull, 0ull, 0ull};
#pragma unroll
            for (int qq = 0; qq < 4; qq++) {
                int idx = mv_base + (((qq + c_blk) & 3) << 3);
                const ull* hq = (const ull*)(hp + idx);
                ull h01 = hq[0], h23 = hq[1];
#pragma unroll
                for (int r = 0; r < 6; r++) acc2[r] = ffma2(W2[r][2*qq+0], h01, acc2[r]);
#pragma unroll
                for (int r = 0; r < 6; r++) acc2[r] = ffma2(W2[r][2*qq+1], h23, acc2[r]);
            }
            float acc[6];
#pragma unroll
            for (int r = 0; r < 6; r++) { float2 f = u2f(acc2[r]); acc[r] = f.x + f.y; }

            // split-butterfly reduce: 6 + 12 + 3 SHFLs
#pragma unroll
            for (int r = 0; r < 6; r++)
                acc[r] += __shfl_xor_sync(0xffffffffu, acc[r], 16);
            bool hihalf = (l >= 16);
            float s0 = hihalf ? acc[3] : acc[0];
            float s1 = hihalf ? acc[4] : acc[1];
            float s2 = hihalf ? acc[5] : acc[2];
#pragma unroll
            for (int off = 8; off > 0; off >>= 1) {
                s0 += __shfl_xor_sync(0xffffffffu, s0, off);
                s1 += __shfl_xor_sync(0xffffffffu, s1, off);
                s2 += __shfl_xor_sync(0xffffffffu, s2, off);
            }
            float t0 = __shfl_sync(0xffffffffu, s0, 16);   // acc3
            float t1 = __shfl_sync(0xffffffffu, s1, 16);   // acc4
            float t2 = __shfl_sync(0xffffffffu, s2, 16);   // acc5

            if (l < 2) {
                int bidx = 2 * w + l;
                float a_r = l ? s1 : s0;
                float a_z = l ? t0 : s2;
                float a_n = l ? t2 : t1;
                float rr = 0.5f * tanhfast(0.5f * (xr + a_r + bhh[bidx]))      + 0.5f;
                float zz = 0.5f * tanhfast(0.5f * (xz + a_z + bhh[32 + bidx])) + 0.5f;
                float nn = tanhfast(xn + rr * (a_n + bhh[64 + bidx]));
                float hnew = fmaf(zz, hold - nn, nn);
                hold = hnew;
                stage[stg_idx] = hnew;
            }
            __syncthreads();   // stage complete; all warps done reading hb[p]

            // bulk publish: ONE 128B DSMEM copy per warp (16 tx updates/dest/step)
            if (l == 0) {
                uint32_t ra = ra_blk + (p ? 0u : 2048u);   // dest buffer p^1
                uint32_t rb = p ? rb_bar0 : rb_bar1;       // bar[p^1]
                asm volatile(
                    "cp.async.bulk.shared::cluster.shared::cta.mbarrier::complete_tx::bytes "
                    "[%0], [%1], 128, [%2];"
                    :: "r"(ra), "r"(stage_u), "r"(rb) : "memory");
            }
            // deferred re-arm of the barrier consumed this step (huge margin:
            // its refill comes from step-s+1 publishers gated on our publish)
            if (did_wait && tid == 0) {
                asm volatile("mbarrier.arrive.expect_tx.shared.b64 _, [%0], %1;"
                             :: "r"(mb_s + 8u * (uint32_t)p), "r"(TX_BYTES) : "memory");
            }
            p ^= 1;
            pending = true;
        }

        if (pending) {
            uint32_t a = mb_s + 8u * (uint32_t)p;
            waitParityCluster(a, p ? ph1 : ph0);
            if (tid == 0)
                asm volatile("mbarrier.arrive.expect_tx.shared.b64 _, [%0], %1;"
                             :: "r"(a), "r"(TX_BYTES) : "memory");
            if (p) ph1 ^= 1; else ph0 ^= 1;
            pending = false;
        }
        // out-write on warp 1 (keeps warp 0, the critical warp, unburdened)
        if (w == 1) {
            out[b * H_ + 32 * (int)c + l] =
                hb[p * 512 + 32 * (int)c + blkoff(l, (int)c)];
        }
    }

    asm volatile("barrier.cluster.arrive.aligned;" ::: "memory");
    asm volatile("barrier.cluster.wait.aligned;"   ::: "memory");
}

// ================= fused kernel =================
__global__ void __launch_bounds__(512, 1)
fused_kernel(const float* __restrict__ visit_emb,
             const float* __restrict__ intervals,
             const float* __restrict__ W_time,
             const float* __restrict__ b_time,
             const float* __restrict__ W_ih,
             const float* __restrict__ W_hh,
             const float* __restrict__ b_ih,
             const float* __restrict__ b_hh,
             const int*   __restrict__ lens,
             float*       __restrict__ out)
{
    extern __shared__ char smc[];
    if (blockIdx.x >= SCAN_CTAS) {
        gemm_body(visit_emb, W_ih, intervals, W_time, b_time, b_ih, smc);
    } else {
        scan_body(W_hh, b_hh, lens, out, smc);
    }
}

// ---------------- launcher ----------------
extern "C" void kernel_launch(void* const* d_in, const int* in_sizes, int n_in,
                              void* d_out, int out_size)
{
    const float* visit_emb = (const float*)d_in[0];
    const float* intervals = (const float*)d_in[1];
    const float* W_time    = (const float*)d_in[2];
    const float* b_time    = (const float*)d_in[3];
    const float* W_ih      = (const float*)d_in[4];
    const float* W_hh      = (const float*)d_in[5];
    const float* b_ih      = (const float*)d_in[6];
    const float* b_hh      = (const float*)d_in[7];
    const int*   lens      = (const int*)d_in[8];
    float* out = (float*)d_out;

    void* readyPtr = nullptr;
    cudaGetSymbolAddress(&readyPtr, g_ready);
    cudaMemsetAsync(readyPtr, 0, 64 * sizeof(unsigned));

    cudaFuncSetAttribute(fused_kernel, cudaFuncAttributeNonPortableClusterSizeAllowed, 1);
    cudaFuncSetAttribute(fused_kernel, cudaFuncAttributeMaxDynamicSharedMemorySize, DYN_SMEM);

    cudaLaunchConfig_t cfg = {};
    cfg.gridDim  = dim3(GRID_X, 1, 1);
    cfg.blockDim = dim3(512, 1, 1);
    cfg.dynamicSmemBytes = DYN_SMEM;
    cfg.stream = 0;
    cudaLaunchAttribute attrs[1];
    attrs[0].id = cudaLaunchAttributeClusterDimension;
    attrs[0].val.clusterDim.x = 16;
    attrs[0].val.clusterDim.y = 1;
    attrs[0].val.clusterDim.z = 1;
    cfg.attrs = attrs;
    cfg.numAttrs = 1;

    cudaLaunchKernelEx(&cfg, fused_kernel,
                       visit_emb, intervals, W_time, b_time, W_ih, W_hh,
                       b_ih, b_hh, lens, out);
}

// round 16
// speedup vs baseline: 1.1579x; 1.0746x over previous
#include <cuda_runtime.h>
#include <cstdint>

#define B_   128
#define T_   64
#define V_   1024
#define TS_  64
#define H_   512
#define NTOK (B_ * T_)      // 8192
#define G3   (3 * H_)       // 1536
#define IN_  (V_ + TS_)     // 1088

typedef unsigned long long ull;

// ---------------- packed fp32x2 helpers (Blackwell) ----------------
__device__ __forceinline__ ull ffma2(ull a, ull b, ull c) {
    ull d;
    asm("fma.rn.f32x2 %0, %1, %2, %3;" : "=l"(d) : "l"(a), "l"(b), "l"(c));
    return d;
}
__device__ __forceinline__ ull dup2(float a) {
    ull d; unsigned u = __float_as_uint(a);
    asm("mov.b64 %0, {%1, %2};" : "=l"(d) : "r"(u), "r"(u));
    return d;
}
__device__ __forceinline__ float2 u2f(ull a) {
    float2 f; unsigned lo, hi;
    asm("mov.b64 {%0, %1}, %2;" : "=r"(lo), "=r"(hi) : "l"(a));
    f.x = __uint_as_float(lo); f.y = __uint_as_float(hi);
    return f;
}
__device__ __forceinline__ float tanhfast(float x) {
    float y; asm("tanh.approx.f32 %0, %1;" : "=f"(y) : "f"(x)); return y;
}

// ---------------- device scratch ----------------
__device__ float    g_xg[NTOK * G3];
__device__ unsigned g_ready[64];          // per 128-token row-tile: #col-tiles done

// ---------------- layout constants ----------------
#define SCAN_CTAS   16
#define GEMM_BLOCKS 768                   // 64 row-tiles x 12 col-tiles
#define GRID_X      (SCAN_CTAS + GEMM_BLOCKS)

#define BM 128
#define BN 128
#define BK 16
#define AST 132

// scan smem layout (dynamic): mbars | hb | stage | bhh | lens
#define SMEM_MBARS  0
#define SMEM_HB     32
#define SMEM_STAGE  (SMEM_HB + 4096)      // 4128: 16B-aligned (cp.async.bulk src)
#define SMEM_BHH    (SMEM_STAGE + 128)
#define SMEM_LENS   (SMEM_BHH + 384)
#define SCAN_BYTES  (SMEM_LENS + 512)
// gemm smem: As | Bs | caS | ccS
#define GEMM_BYTES  (2 * BK * AST * 4 + 2 * BN * 4)
#define DYN_SMEM    ((GEMM_BYTES > SCAN_BYTES ? GEMM_BYTES : SCAN_BYTES) + 128)

// per-phase expected bytes at each dest barrier: 16 src CTAs x 128B = 2048
#define TX_BYTES 2048u

// float index of unit u (0..31) within the 32-float block of source CTA `cta`.
// The (q+cta)&3 swizzle makes every 8-lane quarter's LDS.128 addresses tile
// distinct 16B chunks mod 128B -> conflict-free matvec loads.
__device__ __forceinline__ int blkoff(int u, int cta) {
    int q = (u >> 2) & 3, r = u >> 4, e = u & 3;
    return ((q + cta) & 3) * 8 + r * 4 + e;
}

__device__ __forceinline__ void waitParityCluster(uint32_t addr, int ph) {
    asm volatile(
        "{\n\t"
        ".reg .pred p;\n\t"
        "WLOOP_%=:\n\t"
        "mbarrier.try_wait.parity.acquire.cluster.shared::cta.b64 p, [%0], %1, 0x989680;\n\t"
        "@p bra WDONE_%=;\n\t"
        "bra WLOOP_%=;\n\t"
        "WDONE_%=:\n\t"
        "}"
        :: "r"(addr), "r"(ph) : "memory");
}

// ================= GEMM body (blocks 16..783, 512 threads) =================
// k-loop software-pipelined: LDG for iteration kt+BK prefetched into registers
// before the FFMA block of iteration kt, hiding global-load latency under
// compute + barriers. Shortens every block -> shrinks the scan's startup stall
// (scan waits on row-tile 0 = 12 of these blocks).
__device__ void gemm_body(const float* __restrict__ A,
                          const float* __restrict__ Bw,
                          const float* __restrict__ interval,
                          const float* __restrict__ W_time,
                          const float* __restrict__ b_time,
                          const float* __restrict__ b_ih,
                          char* smc)
{
    float (*As)[AST] = (float (*)[AST])smc;
    float (*Bs)[AST] = (float (*)[AST])(smc + BK * AST * 4);
    float* caS = (float*)(smc + 2 * BK * AST * 4);
    float* ccS = caS + BN;

    int tid = threadIdx.x;
    int gemmIdx = blockIdx.x - SCAN_CTAS;
    int rowTile = gemmIdx / 12;
    int colTile = gemmIdx - rowTile * 12;
    int rowBase = rowTile * BM;
    int colBase = colTile * BN;

    if (tid < BN) {
        int g = colBase + tid;
        const float* wrow = Bw + (size_t)g * IN_ + V_;
        float a = 0.f, cc = 0.f;
#pragma unroll 8
        for (int j = 0; j < TS_; j++) {
            float wv = wrow[j];
            a  += W_time[j] * wv;
            cc += b_time[j] * wv;
        }
        caS[tid] = a;
        ccS[tid] = cc + b_ih[g];
    }

    int tx = tid & 15;
    int ty = tid >> 4;
    int lr = tid >> 2;
    int kq = tid & 3;

    ull acc2[4][4];
#pragma unroll
    for (int i = 0; i < 4; i++)
#pragma unroll
        for (int j = 0; j < 4; j++) acc2[i][j] = 0ull;

    const float* Aptr = A  + (size_t)(rowBase + lr) * V_  + kq * 4;
    const float* Bptr = Bw + (size_t)(colBase + lr) * IN_ + kq * 4;

    // prologue: fetch iteration 0
    float4 a0 = *(const float4*)(Aptr);
    float4 b0 = *(const float4*)(Bptr);

    for (int kt = 0; kt < V_; kt += BK) {
        __syncthreads();
        As[kq*4+0][lr] = a0.x; As[kq*4+1][lr] = a0.y; As[kq*4+2][lr] = a0.z; As[kq*4+3][lr] = a0.w;
        Bs[kq*4+0][lr] = b0.x; Bs[kq*4+1][lr] = b0.y; Bs[kq*4+2][lr] = b0.z; Bs[kq*4+3][lr] = b0.w;
        __syncthreads();

        // prefetch next iteration (clamped, branchless; last iter re-reads)
        int kn = (kt + BK < V_) ? (kt + BK) : kt;
        a0 = *(const float4*)(Aptr + kn);
        b0 = *(const float4*)(Bptr + kn);

#pragma unroll
        for (int kk = 0; kk < BK; kk++) {
            float av[4];
            *(float4*)av = *(const float4*)&As[kk][ty*4];
            const ull* bp = (const ull*)&Bs[kk][tx*8];
            ull bv0 = bp[0], bv1 = bp[1], bv2 = bp[2], bv3 = bp[3];
#pragma unroll
            for (int i = 0; i < 4; i++) {
                ull a2 = dup2(av[i]);
                acc2[i][0] = ffma2(a2, bv0, acc2[i][0]);
                acc2[i][1] = ffma2(a2, bv1, acc2[i][1]);
                acc2[i][2] = ffma2(a2, bv2, acc2[i][2]);
                acc2[i][3] = ffma2(a2, bv3, acc2[i][3]);
            }
        }
    }

    float ai[4], ca[8], cc[8];
#pragma unroll
    for (int i = 0; i < 4; i++) ai[i] = interval[rowBase + ty*4 + i];
#pragma unroll
    for (int j = 0; j < 8; j++) {
        ca[j] = caS[tx*8 + j];
        cc[j] = ccS[tx*8 + j];
    }
#pragma unroll
    for (int i = 0; i < 4; i++) {
        size_t rbase = (size_t)(rowBase + ty*4 + i) * G3 + colBase + tx*8;
#pragma unroll
        for (int q = 0; q < 2; q++) {
            float2 v0 = u2f(acc2[i][2*q+0]);
            float2 v1 = u2f(acc2[i][2*q+1]);
            float4 o;
            o.x = v0.x + ai[i] * ca[4*q+0] + cc[4*q+0];
            o.y = v0.y + ai[i] * ca[4*q+1] + cc[4*q+1];
            o.z = v1.x + ai[i] * ca[4*q+2] + cc[4*q+2];
            o.w = v1.y + ai[i] * ca[4*q+3] + cc[4*q+3];
            *(float4*)&g_xg[rbase + 4*q] = o;
        }
    }

    __syncthreads();
    if (tid == 0) {
        __threadfence();
        atomicAdd(&g_ready[rowTile], 1u);
    }
}

// ================= scan body (blocks 0..15, one 16-CTA cluster) =================
// EXACT R13 (best-known): bulk publish, block layout, 6 reg-resident weight
// rows, pre-matvec re-arm, warp-0 out-writes. Frozen pending SASS evidence.
__device__ void scan_body(const float* __restrict__ W_hh,
                          const float* __restrict__ b_hh,
                          const int*   __restrict__ lens,
                          float*       __restrict__ out,
                          char* smc)
{
    float* hb      = (float*)(smc + SMEM_HB);       // [2][512] block layout
    float* stage   = (float*)(smc + SMEM_STAGE);    // 32 floats, 16B aligned
    float* bhh     = (float*)(smc + SMEM_BHH);
    int*   lens_sm = (int*)(smc + SMEM_LENS);
    uint32_t mb_s  = (uint32_t)__cvta_generic_to_shared(smc + SMEM_MBARS);

    int tid = threadIdx.x;
    int w = tid >> 5;
    int l = tid & 31;
    uint32_t c;
    asm("mov.u32 %0, %%cluster_ctarank;" : "=r"(c));

    hb[tid] = 0.f;
    hb[512 + tid] = 0.f;
    if (tid < 128) lens_sm[tid] = lens[tid];
    if (tid < 96) {
        int g = tid >> 5, u = tid & 31;
        bhh[tid] = b_hh[g * H_ + 32 * (int)c + u];
    }
    if (tid == 0) {
        asm volatile("mbarrier.init.shared.b64 [%0], 1;" :: "r"(mb_s)      : "memory");
        asm volatile("mbarrier.init.shared.b64 [%0], 1;" :: "r"(mb_s + 8) : "memory");
        asm volatile("mbarrier.arrive.expect_tx.shared.b64 _, [%0], %1;"
                     :: "r"(mb_s),     "r"(TX_BYTES) : "memory");
        asm volatile("mbarrier.arrive.expect_tx.shared.b64 _, [%0], %1;"
                     :: "r"(mb_s + 8), "r"(TX_BYTES) : "memory");
        asm volatile("fence.mbarrier_init.release.cluster;" ::: "memory");
    }

    int j0 = 32 * (int)c + 2 * w;

    // all 6 W_hh rows (r0,r1,z0,z1,n0,n1) register-resident as f32x2
    ull W2[6][8];
#pragma unroll
    for (int r = 0; r < 6; r++) {
        int row = (r < 2) ? (j0 + r) : (r < 4) ? (H_ + j0 + r - 2) : (2 * H_ + j0 + r - 4);
        const ull* wp = (const ull*)(W_hh + (size_t)row * H_ + 16 * l);
#pragma unroll
        for (int k = 0; k < 8; k++) W2[r][k] = wp[k];
    }
    __syncthreads();
    asm volatile("barrier.cluster.arrive.aligned;" ::: "memory");
    asm volatile("barrier.cluster.wait.aligned;"   ::: "memory");

    uint32_t hb_u    = (uint32_t)__cvta_generic_to_shared(hb);
    uint32_t stage_u = (uint32_t)__cvta_generic_to_shared(stage);
    // bulk publish addresses: warp w ships stage -> CTA w's block for source c
    uint32_t ra_blk, rb_bar0, rb_bar1;
    {
        uint32_t la = hb_u + 128u * c;      // buffer 0, block c
        asm("mapa.shared::cluster.u32 %0, %1, %2;" : "=r"(ra_blk)  : "r"(la), "r"(w));
        asm("mapa.shared::cluster.u32 %0, %1, %2;" : "=r"(rb_bar0) : "r"(mb_s),     "r"(w));
        asm("mapa.shared::cluster.u32 %0, %1, %2;" : "=r"(rb_bar1) : "r"(mb_s + 8), "r"(w));
    }

    // matvec lane addressing (block layout)
    int c_blk = l >> 1;
    int mv_base = 32 * c_blk + (l & 1) * 4;

    int p = 0, ph0 = 0, ph1 = 0;
    bool pending = false;
    int cur_tile = -1;
    float hold = 0.f;                     // previous hnew of unit j0+l (lanes 0,1)
    int stg_idx = blkoff(2 * w + (l & 1), (int)c);   // gate lane's stage slot

    for (int b = 0; b < B_; b++) {
        int len = lens_sm[b];
        for (int t = 0; t < len; t++) {
            int n = (b << 6) + t;

            // wait until this token's GEMM row-tile is complete (12 col-tiles)
            if ((n >> 7) != cur_tile) {
                cur_tile = n >> 7;
                unsigned rdy;
                do {
                    asm volatile("ld.acquire.gpu.global.u32 %0, [%1];"
                                 : "=r"(rdy) : "l"(g_ready + cur_tile) : "memory");
                } while (rdy < 12u);
            }

            // xg loads issued before the sync wait
            float xr = 0.f, xz = 0.f, xn = 0.f;
            if (l < 2) {
                const float* xp = g_xg + (size_t)n * G3 + (j0 + l);
                xr = __ldg(xp);
                xz = __ldg(xp + H_);
                xn = __ldg(xp + 2 * H_);
            }

            // every warp waits the local barrier; thread 0 re-arms for next use
            if (pending) {
                uint32_t a = mb_s + 8u * (uint32_t)p;
                waitParityCluster(a, p ? ph1 : ph0);
                if (tid == 0)
                    asm volatile("mbarrier.arrive.expect_tx.shared.b64 _, [%0], %1;"
                                 :: "r"(a), "r"(TX_BYTES) : "memory");
                if (p) ph1 ^= 1; else ph0 ^= 1;
                pending = false;
            }

            const float* hp = hb + p * 512;

            ull acc2[6] = {0ull, 0ull, 0ull, 0ull, 0ull, 0ull};
#pragma unroll
            for (int qq = 0; qq < 4; qq++) {
                int idx = mv_base + (((qq + c_blk) & 3) << 3);
                const ull* hq = (const ull*)(hp + idx);
                ull h01 = hq[0], h23 = hq[1];
#pragma unroll
                for (int r = 0; r < 6; r++) acc2[r] = ffma2(W2[r][2*qq+0], h01, acc2[r]);
#pragma unroll
                for (int r = 0; r < 6; r++) acc2[r] = ffma2(W2[r][2*qq+1], h23, acc2[r]);
            }
            float acc[6];
#pragma unroll
            for (int r = 0; r < 6; r++) { float2 f = u2f(acc2[r]); acc[r] = f.x + f.y; }

            // split-butterfly reduce: 6 + 12 + 3 SHFLs
#pragma unroll
            for (int r = 0; r < 6; r++)
                acc[r] += __shfl_xor_sync(0xffffffffu, acc[r], 16);
            bool hihalf = (l >= 16);
            float s0 = hihalf ? acc[3] : acc[0];
            float s1 = hihalf ? acc[4] : acc[1];
            float s2 = hihalf ? acc[5] : acc[2];
#pragma unroll
            for (int off = 8; off > 0; off >>= 1) {
                s0 += __shfl_xor_sync(0xffffffffu, s0, off);
                s1 += __shfl_xor_sync(0xffffffffu, s1, off);
                s2 += __shfl_xor_sync(0xffffffffu, s2, off);
            }
            float t0 = __shfl_sync(0xffffffffu, s0, 16);   // acc3
            float t1 = __shfl_sync(0xffffffffu, s1, 16);   // acc4
            float t2 = __shfl_sync(0xffffffffu, s2, 16);   // acc5

            if (l < 2) {
                int bidx = 2 * w + l;
                float a_r = l ? s1 : s0;
                float a_z = l ? t0 : s2;
                float a_n = l ? t2 : t1;
                float rr = 0.5f * tanhfast(0.5f * (xr + a_r + bhh[bidx]))      + 0.5f;
                float zz = 0.5f * tanhfast(0.5f * (xz + a_z + bhh[32 + bidx])) + 0.5f;
                float nn = tanhfast(xn + rr * (a_n + bhh[64 + bidx]));
                float hnew = fmaf(zz, hold - nn, nn);
                hold = hnew;
                stage[stg_idx] = hnew;
            }
            __syncthreads();   // stage complete; all warps done reading hb[p]

            // bulk publish: ONE 128B DSMEM copy per warp (16 tx updates/dest/step)
            if (l == 0) {
                uint32_t ra = ra_blk + (p ? 0u : 2048u);   // dest buffer p^1
                uint32_t rb = p ? rb_bar0 : rb_bar1;       // bar[p^1]
                asm volatile(
                    "cp.async.bulk.shared::cluster.shared::cta.mbarrier::complete_tx::bytes "
                    "[%0], [%1], 128, [%2];"
                    :: "r"(ra), "r"(stage_u), "r"(rb) : "memory");
            }
            p ^= 1;
            pending = true;
        }

        if (pending) {
            uint32_t a = mb_s + 8u * (uint32_t)p;
            waitParityCluster(a, p ? ph1 : ph0);
            if (tid == 0)
                asm volatile("mbarrier.arrive.expect_tx.shared.b64 _, [%0], %1;"
                             :: "r"(a), "r"(TX_BYTES) : "memory");
            if (p) ph1 ^= 1; else ph0 ^= 1;
            pending = false;
        }
        if (tid < 32) {
            out[b * H_ + 32 * (int)c + tid] =
                hb[p * 512 + 32 * (int)c + blkoff(tid, (int)c)];
        }
    }

    asm volatile("barrier.cluster.arrive.aligned;" ::: "memory");
    asm volatile("barrier.cluster.wait.aligned;"   ::: "memory");
}

// ================= fused kernel =================
__global__ void __launch_bounds__(512, 1)
fused_kernel(const float* __restrict__ visit_emb,
             const float* __restrict__ intervals,
             const float* __restrict__ W_time,
             const float* __restrict__ b_time,
             const float* __restrict__ W_ih,
             const float* __restrict__ W_hh,
             const float* __restrict__ b_ih,
             const float* __restrict__ b_hh,
             const int*   __restrict__ lens,
             float*       __restrict__ out)
{
    extern __shared__ char smc[];
    if (blockIdx.x >= SCAN_CTAS) {
        gemm_body(visit_emb, W_ih, intervals, W_time, b_time, b_ih, smc);
    } else {
        scan_body(W_hh, b_hh, lens, out, smc);
    }
}

// ---------------- launcher ----------------
extern "C" void kernel_launch(void* const* d_in, const int* in_sizes, int n_in,
                              void* d_out, int out_size)
{
    const float* visit_emb = (const float*)d_in[0];
    const float* intervals = (const float*)d_in[1];
    const float* W_time    = (const float*)d_in[2];
    const float* b_time    = (const float*)d_in[3];
    const float* W_ih      = (const float*)d_in[4];
    const float* W_hh      = (const float*)d_in[5];
    const float* b_ih      = (const float*)d_in[6];
    const float* b_hh      = (const float*)d_in[7];
    const int*   lens      = (const int*)d_in[8];
    float* out = (float*)d_out;

    void* readyPtr = nullptr;
    cudaGetSymbolAddress(&readyPtr, g_ready);
    cudaMemsetAsync(readyPtr, 0, 64 * sizeof(unsigned));

    cudaFuncSetAttribute(fused_kernel, cudaFuncAttributeNonPortableClusterSizeAllowed, 1);
    cudaFuncSetAttribute(fused_kernel, cudaFuncAttributeMaxDynamicSharedMemorySize, DYN_SMEM);

    cudaLaunchConfig_t cfg = {};
    cfg.gridDim  = dim3(GRID_X, 1, 1);
    cfg.blockDim = dim3(512, 1, 1);
    cfg.dynamicSmemBytes = DYN_SMEM;
    cfg.stream = 0;
    cudaLaunchAttribute attrs[1];
    attrs[0].id = cudaLaunchAttributeClusterDimension;
    attrs[0].val.clusterDim.x = 16;
    attrs[0].val.clusterDim.y = 1;
    attrs[0].val.clusterDim.z = 1;
    cfg.attrs = attrs;
    cfg.numAttrs = 1;

    cudaLaunchKernelEx(&cfg, fused_kernel,
                       visit_emb, intervals, W_time, b_time, W_ih, W_hh,
                       b_ih, b_hh, lens, out);
}

// round 17
// speedup vs baseline: 1.1664x; 1.0074x over previous
#include <cuda_runtime.h>
#include <cstdint>

#define B_   128
#define T_   64
#define V_   1024
#define TS_  64
#define H_   512
#define NTOK (B_ * T_)      // 8192
#define G3   (3 * H_)       // 1536
#define IN_  (V_ + TS_)     // 1088

typedef unsigned long long ull;

// ---------------- packed fp32x2 helpers (Blackwell) ----------------
__device__ __forceinline__ ull ffma2(ull a, ull b, ull c) {
    ull d;
    asm("fma.rn.f32x2 %0, %1, %2, %3;" : "=l"(d) : "l"(a), "l"(b), "l"(c));
    return d;
}
__device__ __forceinline__ ull dup2(float a) {
    ull d; unsigned u = __float_as_uint(a);
    asm("mov.b64 %0, {%1, %2};" : "=l"(d) : "r"(u), "r"(u));
    return d;
}
__device__ __forceinline__ float2 u2f(ull a) {
    float2 f; unsigned lo, hi;
    asm("mov.b64 {%0, %1}, %2;" : "=r"(lo), "=r"(hi) : "l"(a));
    f.x = __uint_as_float(lo); f.y = __uint_as_float(hi);
    return f;
}
__device__ __forceinline__ float tanhfast(float x) {
    float y; asm("tanh.approx.f32 %0, %1;" : "=f"(y) : "f"(x)); return y;
}

// ---------------- device scratch ----------------
__device__ float    g_xg[NTOK * G3];
__device__ unsigned g_ready[128];         // per 64-token row-tile: #col-tiles done

// ---------------- layout constants ----------------
#define SCAN_CTAS   16
#define ROW_TILES   128                   // 64 tokens each
#define GEMM_BLOCKS (ROW_TILES * 12)      // 1536
#define GRID_X      (SCAN_CTAS + GEMM_BLOCKS)

#define BM 64
#define BN 128
#define BK 16
#define AST 132

// scan smem layout (dynamic): mbars | hb | stage | bhh | lens
#define SMEM_MBARS  0
#define SMEM_HB     32
#define SMEM_STAGE  (SMEM_HB + 4096)      // 4128: 16B-aligned (cp.async.bulk src)
#define SMEM_BHH    (SMEM_STAGE + 128)
#define SMEM_LENS   (SMEM_BHH + 384)
#define SCAN_BYTES  (SMEM_LENS + 512)
// gemm smem: As | Bs | caS | ccS  (As uses AST stride for layout uniformity)
#define GEMM_BYTES  (2 * BK * AST * 4 + 2 * BN * 4)
#define DYN_SMEM    ((GEMM_BYTES > SCAN_BYTES ? GEMM_BYTES : SCAN_BYTES) + 128)

// per-phase expected bytes at each dest barrier: 16 src CTAs x 128B = 2048
#define TX_BYTES 2048u

// float index of unit u (0..31) within the 32-float block of source CTA `cta`.
// The (q+cta)&3 swizzle makes every 8-lane quarter's LDS.128 addresses tile
// distinct 16B chunks mod 128B -> conflict-free matvec loads.
__device__ __forceinline__ int blkoff(int u, int cta) {
    int q = (u >> 2) & 3, r = u >> 4, e = u & 3;
    return ((q + cta) & 3) * 8 + r * 4 + e;
}

__device__ __forceinline__ void waitParityCluster(uint32_t addr, int ph) {
    asm volatile(
        "{\n\t"
        ".reg .pred p;\n\t"
        "WLOOP_%=:\n\t"
        "mbarrier.try_wait.parity.acquire.cluster.shared::cta.b64 p, [%0], %1, 0x989680;\n\t"
        "@p bra WDONE_%=;\n\t"
        "bra WLOOP_%=;\n\t"
        "WDONE_%=:\n\t"
        "}"
        :: "r"(addr), "r"(ph) : "memory");
}

// ================= GEMM body (blocks 16.., 512 threads, BM=64) =================
// Narrow row-tiles (64 tokens) halve per-block duration -> halve the scan's
// startup stall on row-tile 0. Register-prefetch k-pipeline kept from R16.
__device__ void gemm_body(const float* __restrict__ A,
                          const float* __restrict__ Bw,
                          const float* __restrict__ interval,
                          const float* __restrict__ W_time,
                          const float* __restrict__ b_time,
                          const float* __restrict__ b_ih,
                          char* smc)
{
    float (*As)[AST] = (float (*)[AST])smc;
    float (*Bs)[AST] = (float (*)[AST])(smc + BK * AST * 4);
    float* caS = (float*)(smc + 2 * BK * AST * 4);
    float* ccS = caS + BN;

    int tid = threadIdx.x;
    int gemmIdx = blockIdx.x - SCAN_CTAS;
    int rowTile = gemmIdx / 12;
    int colTile = gemmIdx - rowTile * 12;
    int rowBase = rowTile * BM;
    int colBase = colTile * BN;

    if (tid < BN) {
        int g = colBase + tid;
        const float* wrow = Bw + (size_t)g * IN_ + V_;
        float a = 0.f, cc = 0.f;
#pragma unroll 8
        for (int j = 0; j < TS_; j++) {
            float wv = wrow[j];
            a  += W_time[j] * wv;
            cc += b_time[j] * wv;
        }
        caS[tid] = a;
        ccS[tid] = cc + b_ih[g];
    }

    int tx = tid & 15;          // 8 cols each
    int ty = tid >> 4;          // 0..31 -> 2 rows each
    int lr = tid >> 2;          // B rows (0..127); A rows = lr for tid<256
    int kq = tid & 3;

    ull acc2[2][4];
#pragma unroll
    for (int i = 0; i < 2; i++)
#pragma unroll
        for (int j = 0; j < 4; j++) acc2[i][j] = 0ull;

    const float* Aptr = A  + (size_t)(rowBase + lr) * V_  + kq * 4;   // valid tid<256
    const float* Bptr = Bw + (size_t)(colBase + lr) * IN_ + kq * 4;

    // prologue: fetch iteration 0
    float4 a0 = make_float4(0.f, 0.f, 0.f, 0.f);
    if (tid < 256) a0 = *(const float4*)(Aptr);
    float4 b0 = *(const float4*)(Bptr);

    for (int kt = 0; kt < V_; kt += BK) {
        __syncthreads();
        if (tid < 256) {
            As[kq*4+0][lr] = a0.x; As[kq*4+1][lr] = a0.y;
            As[kq*4+2][lr] = a0.z; As[kq*4+3][lr] = a0.w;
        }
        Bs[kq*4+0][lr] = b0.x; Bs[kq*4+1][lr] = b0.y;
        Bs[kq*4+2][lr] = b0.z; Bs[kq*4+3][lr] = b0.w;
        __syncthreads();

        // prefetch next iteration (clamped, branchless index; last iter re-reads)
        int kn = (kt + BK < V_) ? (kt + BK) : kt;
        if (tid < 256) a0 = *(const float4*)(Aptr + kn);
        b0 = *(const float4*)(Bptr + kn);

#pragma unroll
        for (int kk = 0; kk < BK; kk++) {
            float2 av = *(const float2*)&As[kk][ty*2];
            const ull* bp = (const ull*)&Bs[kk][tx*8];
            ull bv0 = bp[0], bv1 = bp[1], bv2 = bp[2], bv3 = bp[3];
            ull a2x = dup2(av.x);
            acc2[0][0] = ffma2(a2x, bv0, acc2[0][0]);
            acc2[0][1] = ffma2(a2x, bv1, acc2[0][1]);
            acc2[0][2] = ffma2(a2x, bv2, acc2[0][2]);
            acc2[0][3] = ffma2(a2x, bv3, acc2[0][3]);
            ull a2y = dup2(av.y);
            acc2[1][0] = ffma2(a2y, bv0, acc2[1][0]);
            acc2[1][1] = ffma2(a2y, bv1, acc2[1][1]);
            acc2[1][2] = ffma2(a2y, bv2, acc2[1][2]);
            acc2[1][3] = ffma2(a2y, bv3, acc2[1][3]);
        }
    }

    float ai[2], ca[8], cc[8];
#pragma unroll
    for (int i = 0; i < 2; i++) ai[i] = interval[rowBase + ty*2 + i];
#pragma unroll
    for (int j = 0; j < 8; j++) {
        ca[j] = caS[tx*8 + j];
        cc[j] = ccS[tx*8 + j];
    }
#pragma unroll
    for (int i = 0; i < 2; i++) {
        size_t rbase = (size_t)(rowBase + ty*2 + i) * G3 + colBase + tx*8;
#pragma unroll
        for (int q = 0; q < 2; q++) {
            float2 v0 = u2f(acc2[i][2*q+0]);
            float2 v1 = u2f(acc2[i][2*q+1]);
            float4 o;
            o.x = v0.x + ai[i] * ca[4*q+0] + cc[4*q+0];
            o.y = v0.y + ai[i] * ca[4*q+1] + cc[4*q+1];
            o.z = v1.x + ai[i] * ca[4*q+2] + cc[4*q+2];
            o.w = v1.y + ai[i] * ca[4*q+3] + cc[4*q+3];
            *(float4*)&g_xg[rbase + 4*q] = o;
        }
    }

    __syncthreads();
    if (tid == 0) {
        __threadfence();
        atomicAdd(&g_ready[rowTile], 1u);
    }
}

// ================= scan body (blocks 0..15, one 16-CTA cluster) =================
// EXACT R13 (best-known): bulk publish, block layout, 6 reg-resident weight
// rows, pre-matvec re-arm, warp-0 out-writes. Frozen pending SASS evidence.
// Only change: row-tile readiness granularity is now 64 tokens (n>>6).
__device__ void scan_body(const float* __restrict__ W_hh,
                          const float* __restrict__ b_hh,
                          const int*   __restrict__ lens,
                          float*       __restrict__ out,
                          char* smc)
{
    float* hb      = (float*)(smc + SMEM_HB);       // [2][512] block layout
    float* stage   = (float*)(smc + SMEM_STAGE);    // 32 floats, 16B aligned
    float* bhh     = (float*)(smc + SMEM_BHH);
    int*   lens_sm = (int*)(smc + SMEM_LENS);
    uint32_t mb_s  = (uint32_t)__cvta_generic_to_shared(smc + SMEM_MBARS);

    int tid = threadIdx.x;
    int w = tid >> 5;
    int l = tid & 31;
    uint32_t c;
    asm("mov.u32 %0, %%cluster_ctarank;" : "=r"(c));

    hb[tid] = 0.f;
    hb[512 + tid] = 0.f;
    if (tid < 128) lens_sm[tid] = lens[tid];
    if (tid < 96) {
        int g = tid >> 5, u = tid & 31;
        bhh[tid] = b_hh[g * H_ + 32 * (int)c + u];
    }
    if (tid == 0) {
        asm volatile("mbarrier.init.shared.b64 [%0], 1;" :: "r"(mb_s)      : "memory");
        asm volatile("mbarrier.init.shared.b64 [%0], 1;" :: "r"(mb_s + 8) : "memory");
        asm volatile("mbarrier.arrive.expect_tx.shared.b64 _, [%0], %1;"
                     :: "r"(mb_s),     "r"(TX_BYTES) : "memory");
        asm volatile("mbarrier.arrive.expect_tx.shared.b64 _, [%0], %1;"
                     :: "r"(mb_s + 8), "r"(TX_BYTES) : "memory");
        asm volatile("fence.mbarrier_init.release.cluster;" ::: "memory");
    }

    int j0 = 32 * (int)c + 2 * w;

    // all 6 W_hh rows (r0,r1,z0,z1,n0,n1) register-resident as f32x2
    ull W2[6][8];
#pragma unroll
    for (int r = 0; r < 6; r++) {
        int row = (r < 2) ? (j0 + r) : (r < 4) ? (H_ + j0 + r - 2) : (2 * H_ + j0 + r - 4);
        const ull* wp = (const ull*)(W_hh + (size_t)row * H_ + 16 * l);
#pragma unroll
        for (int k = 0; k < 8; k++) W2[r][k] = wp[k];
    }
    __syncthreads();
    asm volatile("barrier.cluster.arrive.aligned;" ::: "memory");
    asm volatile("barrier.cluster.wait.aligned;"   ::: "memory");

    uint32_t hb_u    = (uint32_t)__cvta_generic_to_shared(hb);
    uint32_t stage_u = (uint32_t)__cvta_generic_to_shared(stage);
    // bulk publish addresses: warp w ships stage -> CTA w's block for source c
    uint32_t ra_blk, rb_bar0, rb_bar1;
    {
        uint32_t la = hb_u + 128u * c;      // buffer 0, block c
        asm("mapa.shared::cluster.u32 %0, %1, %2;" : "=r"(ra_blk)  : "r"(la), "r"(w));
        asm("mapa.shared::cluster.u32 %0, %1, %2;" : "=r"(rb_bar0) : "r"(mb_s),     "r"(w));
        asm("mapa.shared::cluster.u32 %0, %1, %2;" : "=r"(rb_bar1) : "r"(mb_s + 8), "r"(w));
    }

    // matvec lane addressing (block layout)
    int c_blk = l >> 1;
    int mv_base = 32 * c_blk + (l & 1) * 4;

    int p = 0, ph0 = 0, ph1 = 0;
    bool pending = false;
    int cur_tile = -1;
    float hold = 0.f;                     // previous hnew of unit j0+l (lanes 0,1)
    int stg_idx = blkoff(2 * w + (l & 1), (int)c);   // gate lane's stage slot

    for (int b = 0; b < B_; b++) {
        int len = lens_sm[b];
        for (int t = 0; t < len; t++) {
            int n = (b << 6) + t;

            // wait until this token's GEMM row-tile is complete (12 col-tiles)
            if ((n >> 6) != cur_tile) {
                cur_tile = n >> 6;
                unsigned rdy;
                do {
                    asm volatile("ld.acquire.gpu.global.u32 %0, [%1];"
                                 : "=r"(rdy) : "l"(g_ready + cur_tile) : "memory");
                } while (rdy < 12u);
            }

            // xg loads issued before the sync wait
            float xr = 0.f, xz = 0.f, xn = 0.f;
            if (l < 2) {
                const float* xp = g_xg + (size_t)n * G3 + (j0 + l);
                xr = __ldg(xp);
                xz = __ldg(xp + H_);
                xn = __ldg(xp + 2 * H_);
            }

            // every warp waits the local barrier; thread 0 re-arms for next use
            if (pending) {
                uint32_t a = mb_s + 8u * (uint32_t)p;
                waitParityCluster(a, p ? ph1 : ph0);
                if (tid == 0)
                    asm volatile("mbarrier.arrive.expect_tx.shared.b64 _, [%0], %1;"
                                 :: "r"(a), "r"(TX_BYTES) : "memory");
                if (p) ph1 ^= 1; else ph0 ^= 1;
                pending = false;
            }

            const float* hp = hb + p * 512;

            ull acc2[6] = {0ull, 0ull, 0ull, 0ull, 0ull, 0ull};
#pragma unroll
            for (int qq = 0; qq < 4; qq++) {
                int idx = mv_base + (((qq + c_blk) & 3) << 3);
                const ull* hq = (const ull*)(hp + idx);
                ull h01 = hq[0], h23 = hq[1];
#pragma unroll
                for (int r = 0; r < 6; r++) acc2[r] = ffma2(W2[r][2*qq+0], h01, acc2[r]);
#pragma unroll
                for (int r = 0; r < 6; r++) acc2[r] = ffma2(W2[r][2*qq+1], h23, acc2[r]);
            }
            float acc[6];
#pragma unroll
            for (int r = 0; r < 6; r++) { float2 f = u2f(acc2[r]); acc[r] = f.x + f.y; }

            // split-butterfly reduce: 6 + 12 + 3 SHFLs
#pragma unroll
            for (int r = 0; r < 6; r++)
                acc[r] += __shfl_xor_sync(0xffffffffu, acc[r], 16);
            bool hihalf = (l >= 16);
            float s0 = hihalf ? acc[3] : acc[0];
            float s1 = hihalf ? acc[4] : acc[1];
            float s2 = hihalf ? acc[5] : acc[2];
#pragma unroll
            for (int off = 8; off > 0; off >>= 1) {
                s0 += __shfl_xor_sync(0xffffffffu, s0, off);
                s1 += __shfl_xor_sync(0xffffffffu, s1, off);
                s2 += __shfl_xor_sync(0xffffffffu, s2, off);
            }
            float t0 = __shfl_sync(0xffffffffu, s0, 16);   // acc3
            float t1 = __shfl_sync(0xffffffffu, s1, 16);   // acc4
            float t2 = __shfl_sync(0xffffffffu, s2, 16);   // acc5

            if (l < 2) {
                int bidx = 2 * w + l;
                float a_r = l ? s1 : s0;
                float a_z = l ? t0 : s2;
                float a_n = l ? t2 : t1;
                float rr = 0.5f * tanhfast(0.5f * (xr + a_r + bhh[bidx]))      + 0.5f;
                float zz = 0.5f * tanhfast(0.5f * (xz + a_z + bhh[32 + bidx])) + 0.5f;
                float nn = tanhfast(xn + rr * (a_n + bhh[64 + bidx]));
                float hnew = fmaf(zz, hold - nn, nn);
                hold = hnew;
                stage[stg_idx] = hnew;
            }
            __syncthreads();   // stage complete; all warps done reading hb[p]

            // bulk publish: ONE 128B DSMEM copy per warp (16 tx updates/dest/step)
            if (l == 0) {
                uint32_t ra = ra_blk + (p ? 0u : 2048u);   // dest buffer p^1
                uint32_t rb = p ? rb_bar0 : rb_bar1;       // bar[p^1]
                asm volatile(
                    "cp.async.bulk.shared::cluster.shared::cta.mbarrier::complete_tx::bytes "
                    "[%0], [%1], 128, [%2];"
                    :: "r"(ra), "r"(stage_u), "r"(rb) : "memory");
            }
            p ^= 1;
            pending = true;
        }

        if (pending) {
            uint32_t a = mb_s + 8u * (uint32_t)p;
            waitParityCluster(a, p ? ph1 : ph0);
            if (tid == 0)
                asm volatile("mbarrier.arrive.expect_tx.shared.b64 _, [%0], %1;"
                             :: "r"(a), "r"(TX_BYTES) : "memory");
            if (p) ph1 ^= 1; else ph0 ^= 1;
            pending = false;
        }
        if (tid < 32) {
            out[b * H_ + 32 * (int)c + tid] =
                hb[p * 512 + 32 * (int)c + blkoff(tid, (int)c)];
        }
    }

    asm volatile("barrier.cluster.arrive.aligned;" ::: "memory");
    asm volatile("barrier.cluster.wait.aligned;"   ::: "memory");
}

// ================= fused kernel =================
__global__ void __launch_bounds__(512, 1)
fused_kernel(const float* __restrict__ visit_emb,
             const float* __restrict__ intervals,
             const float* __restrict__ W_time,
             const float* __restrict__ b_time,
             const float* __restrict__ W_ih,
             const float* __restrict__ W_hh,
             const float* __restrict__ b_ih,
             const float* __restrict__ b_hh,
             const int*   __restrict__ lens,
             float*       __restrict__ out)
{
    extern __shared__ char smc[];
    if (blockIdx.x >= SCAN_CTAS) {
        gemm_body(visit_emb, W_ih, intervals, W_time, b_time, b_ih, smc);
    } else {
        scan_body(W_hh, b_hh, lens, out, smc);
    }
}

// ---------------- launcher ----------------
extern "C" void kernel_launch(void* const* d_in, const int* in_sizes, int n_in,
                              void* d_out, int out_size)
{
    const float* visit_emb = (const float*)d_in[0];
    const float* intervals = (const float*)d_in[1];
    const float* W_time    = (const float*)d_in[2];
    const float* b_time    = (const float*)d_in[3];
    const float* W_ih      = (const float*)d_in[4];
    const float* W_hh      = (const float*)d_in[5];
    const float* b_ih      = (const float*)d_in[6];
    const float* b_hh      = (const float*)d_in[7];
    const int*   lens      = (const int*)d_in[8];
    float* out = (float*)d_out;

    void* readyPtr = nullptr;
    cudaGetSymbolAddress(&readyPtr, g_ready);
    cudaMemsetAsync(readyPtr, 0, 128 * sizeof(unsigned));

    cudaFuncSetAttribute(fused_kernel, cudaFuncAttributeNonPortableClusterSizeAllowed, 1);
    cudaFuncSetAttribute(fused_kernel, cudaFuncAttributeMaxDynamicSharedMemorySize, DYN_SMEM);

    cudaLaunchConfig_t cfg = {};
    cfg.gridDim  = dim3(GRID_X, 1, 1);
    cfg.blockDim = dim3(512, 1, 1);
    cfg.dynamicSmemBytes = DYN_SMEM;
    cfg.stream = 0;
    cudaLaunchAttribute attrs[1];
    attrs[0].id = cudaLaunchAttributeClusterDimension;
    attrs[0].val.clusterDim.x = 16;
    attrs[0].val.clusterDim.y = 1;
    attrs[0].val.clusterDim.z = 1;
    cfg.attrs = attrs;
    cfg.numAttrs = 1;

    cudaLaunchKernelEx(&cfg, fused_kernel,
                       visit_emb, intervals, W_time, b_time, W_ih, W_hh,
                       b_ih, b_hh, lens, out);
}